// round 7
// baseline (speedup 1.0000x reference)
#include <cuda_runtime.h>

#define N_NODES 50000
#define N_EDGES 800000
#define FDIM 64
#define N_TILES ((N_NODES + 31) / 32)   // 1563

// ---------------- device scratch ----------------
__device__ int   g_src[N_EDGES];
__device__ int   g_dst[N_EDGES];
__device__ int   g_csrc[N_EDGES];          // CSR: src ids grouped by dst
__device__ int   g_row[N_NODES];           // CSR slice start per dst (arbitrary order)
__device__ int   g_cnt[N_NODES + 1];       // in-degree histogram; [N] = global offset counter
__device__ int   g_cur[N_NODES];           // scatter cursors
__device__ __align__(16) float g_aggG[N_NODES * FDIM];
__device__ __align__(16) float g_aggA[N_NODES * FDIM];
__device__ __align__(16) float g_aggS[N_NODES * FDIM];
__device__ float g_ssrc[N_NODES];
__device__ float g_sdst[N_NODES];
__device__ float g_dinv[N_NODES];

__device__ __forceinline__ float lrelu(float v) { return v > 0.f ? v : 0.2f * v; }

// ---------------- 0: dtype-detect + convert + histogram + per-node attn scalars ----------------
// int64 detection: ids < 50000 so high 32-bit words are 0; if int32, the odd
// words are 64 random ids (all-zero prob ~ (1/50000)^64 ~ 0).
__global__ void k_convert(const void* __restrict__ ei, const float* __restrict__ x,
                          const float* __restrict__ Wa, const float* __restrict__ as_,
                          const float* __restrict__ ad_) {
    __shared__ int s_is64;
    __shared__ float sva[FDIM], svb[FDIM];
    const unsigned int* w = (const unsigned int*)ei;
    int gid = blockIdx.x * blockDim.x + threadIdx.x;

    if (threadIdx.x == 0) {
        int z = 1;
        for (int i = 0; i < 64; i++) if (w[2 * i + 1] != 0u) { z = 0; break; }
        s_is64 = z;
    }
    if (blockIdx.x * blockDim.x < N_NODES) {
        if (threadIdx.x < FDIM) {
            int k = threadIdx.x;
            float va = 0.f, vb = 0.f;
            #pragma unroll 8
            for (int j = 0; j < FDIM; j++) {
                float wv = Wa[k * FDIM + j];
                va = fmaf(wv, as_[j], va);
                vb = fmaf(wv, ad_[j], vb);
            }
            sva[k] = va;
            svb[k] = vb;
        }
        __syncthreads();
        if (gid < N_NODES) {
            const float4* xr = (const float4*)(x + (size_t)gid * FDIM);
            float ss = 0.f, sd = 0.f;
            #pragma unroll
            for (int i = 0; i < FDIM / 4; i++) {
                float4 v = xr[i];
                ss = fmaf(v.x, sva[4*i], fmaf(v.y, sva[4*i+1], fmaf(v.z, sva[4*i+2], fmaf(v.w, sva[4*i+3], ss))));
                sd = fmaf(v.x, svb[4*i], fmaf(v.y, svb[4*i+1], fmaf(v.z, svb[4*i+2], fmaf(v.w, svb[4*i+3], sd))));
            }
            g_ssrc[gid] = ss;
            g_sdst[gid] = sd;
        }
    } else {
        __syncthreads();
    }
    int is64 = s_is64;
    int stride = gridDim.x * blockDim.x;
    for (int i = gid; i < 2 * N_EDGES; i += stride) {
        int v;
        if (is64) v = (int)((const long long*)ei)[i];
        else      v = ((const int*)ei)[i];
        if (i < N_EDGES) g_src[i] = v;
        else {
            g_dst[i - N_EDGES] = v;
            atomicAdd(&g_cnt[v], 1);
        }
    }
}

// ---------------- 1: row-slice assignment (block scan + 1 atomic per block) ----------------
__global__ void k_rowassign() {
    __shared__ int s_warp[8];
    __shared__ int s_base;
    int tid = threadIdx.x;
    int n = blockIdx.x * 256 + tid;
    int lane = tid & 31, wid = tid >> 5;
    int c = (n < N_NODES) ? g_cnt[n] : 0;
    int v = c;
    #pragma unroll
    for (int off = 1; off < 32; off <<= 1) {
        int u = __shfl_up_sync(0xffffffffu, v, off);
        if (lane >= off) v += u;
    }
    if (lane == 31) s_warp[wid] = v;
    __syncthreads();
    if (tid < 8) {
        int pv = s_warp[tid];
        #pragma unroll
        for (int off = 1; off < 8; off <<= 1) {
            int u = __shfl_up_sync(0xffu, pv, off);
            if (tid >= off) pv += u;
        }
        s_warp[tid] = pv;
        if (tid == 7) s_base = atomicAdd(&g_cnt[N_NODES], pv);
    }
    __syncthreads();
    int excl = v - c + (wid > 0 ? s_warp[wid - 1] : 0);
    if (n < N_NODES) {
        g_row[n] = s_base + excl;
        g_cur[n] = 0;
        g_dinv[n] = rsqrtf((float)c + 1.0f);
    }
}

// ---------------- 2: scatter src into CSR ----------------
__global__ void k_scatter() {
    int stride = gridDim.x * blockDim.x;
    for (int e = blockIdx.x * blockDim.x + threadIdx.x; e < N_EDGES; e += stride) {
        int d = g_dst[e];
        int pos = g_row[d] + atomicAdd(&g_cur[d], 1);
        g_csrc[pos] = g_src[e];
    }
}

// ---------------- 3: warp-per-node aggregation (smem scalar broadcast, no branches) ----------------
__global__ void __launch_bounds__(256) k_agg(const float* __restrict__ x) {
    __shared__ float4 sEd[8][32];
    int wib = threadIdx.x >> 5;
    int wid = (blockIdx.x * blockDim.x + threadIdx.x) >> 5;
    int lane = threadIdx.x & 31;
    if (wid >= N_NODES) return;
    int d = wid;
    int row = g_row[d], end = row + g_cnt[d];
    float sd = g_sdst[d];
    float dvd = g_dinv[d];
    int q = lane & 15, half = lane >> 4;
    const float4* x4 = (const float4*)x;

    float4 aG = make_float4(0.f, 0.f, 0.f, 0.f);
    float4 aA = aG, aS = aG;
    float denom = 0.f;

    for (int base = row; base < end; base += 32) {
        int m = min(32, end - base);
        // phase A: one edge per lane — per-edge scalars computed once, staged to smem
        int   s_r = 0;
        float we_r = 0.f, wg_r = 0.f, ws_r = 0.f;
        if (lane < m) {
            s_r = g_csrc[base + lane];
            we_r = expf(lrelu(g_ssrc[s_r] + sd));
            wg_r = g_dinv[s_r] * dvd;
            ws_r = 1.f;
            denom += we_r;
        }
        sEd[wib][lane] = make_float4(__int_as_float(s_r), we_r, wg_r, ws_r);
        __syncwarp();
        // phase B: half-warp per edge, 4 edges per iteration, weights kill padding
        int mp = (m + 3) & ~3;
        for (int i2 = 0; i2 < mp; i2 += 4) {
            float4 eA = sEd[wib][i2 + half];
            float4 eB = sEd[wib][i2 + 2 + half];
            float4 xvA = x4[__float_as_int(eA.x) * 16 + q];
            float4 xvB = x4[__float_as_int(eB.x) * 16 + q];
            aG.x = fmaf(eA.z, xvA.x, aG.x); aG.y = fmaf(eA.z, xvA.y, aG.y);
            aG.z = fmaf(eA.z, xvA.z, aG.z); aG.w = fmaf(eA.z, xvA.w, aG.w);
            aA.x = fmaf(eA.y, xvA.x, aA.x); aA.y = fmaf(eA.y, xvA.y, aA.y);
            aA.z = fmaf(eA.y, xvA.z, aA.z); aA.w = fmaf(eA.y, xvA.w, aA.w);
            aS.x = fmaf(eA.w, xvA.x, aS.x); aS.y = fmaf(eA.w, xvA.y, aS.y);
            aS.z = fmaf(eA.w, xvA.z, aS.z); aS.w = fmaf(eA.w, xvA.w, aS.w);
            aG.x = fmaf(eB.z, xvB.x, aG.x); aG.y = fmaf(eB.z, xvB.y, aG.y);
            aG.z = fmaf(eB.z, xvB.z, aG.z); aG.w = fmaf(eB.z, xvB.w, aG.w);
            aA.x = fmaf(eB.y, xvB.x, aA.x); aA.y = fmaf(eB.y, xvB.y, aA.y);
            aA.z = fmaf(eB.y, xvB.z, aA.z); aA.w = fmaf(eB.y, xvB.w, aA.w);
            aS.x = fmaf(eB.w, xvB.x, aS.x); aS.y = fmaf(eB.w, xvB.y, aS.y);
            aS.z = fmaf(eB.w, xvB.z, aS.z); aS.w = fmaf(eB.w, xvB.w, aS.w);
        }
        __syncwarp();
    }

    #pragma unroll
    for (int off = 16; off > 0; off >>= 1)
        denom += __shfl_xor_sync(0xffffffffu, denom, off);
    float selfexp = expf(lrelu(g_ssrc[d] + sd));
    float rdenom = 1.0f / (denom + selfexp);

    #pragma unroll
    for (int c = 0; c < 12; c++) {
        float* p = (c < 4) ? (&aG.x + c) : (c < 8) ? (&aA.x + (c - 4)) : (&aS.x + (c - 8));
        *p += __shfl_xor_sync(0xffffffffu, *p, 16);
    }
    if (half == 0) {
        float4 xd = x4[d * 16 + q];
        float wd = dvd * dvd;
        float4 G = make_float4(fmaf(wd, xd.x, aG.x), fmaf(wd, xd.y, aG.y),
                               fmaf(wd, xd.z, aG.z), fmaf(wd, xd.w, aG.w));
        float4 A = make_float4((aA.x + selfexp * xd.x) * rdenom, (aA.y + selfexp * xd.y) * rdenom,
                               (aA.z + selfexp * xd.z) * rdenom, (aA.w + selfexp * xd.w) * rdenom);
        ((float4*)g_aggG)[d * 16 + q] = G;
        ((float4*)g_aggA)[d * 16 + q] = A;
        ((float4*)g_aggS)[d * 16 + q] = aS;
    }
}

// ---------------- 4: register-blocked 5-panel GEMM + epilogue ----------------
// panels: 0: aggG@Wg  1: aggA@Wa  2: (aggS*ci)@Wl  3: x@Wr  4: (x+aggS)@Wi
// smem float layout:
//   sW   [5][64][64]      @ 0        (20480)
//   sWo  [4][64]          @ 20480    (256)
//   sBias[4][64]          @ 20736    (256)
//   sU   [5][64][32]      @ 20992    (10240)  inputs transposed [k][node]
//   sP   [5][32][65]      @ 31232    (10400)  panel outputs, padded rows
//   sCi  [32]             @ 41632    (32)
#define KF_SMEM_FLOATS 41664
#define KF_SMEM_BYTES (KF_SMEM_FLOATS * 4)

__global__ void __launch_bounds__(320, 1) k_final(
        const float* __restrict__ x,
        const float* __restrict__ Wg, const float* __restrict__ bg,
        const float* __restrict__ Wa, const float* __restrict__ ba,
        const float* __restrict__ Wl, const float* __restrict__ bl,
        const float* __restrict__ Wr,
        const float* __restrict__ Wi, const float* __restrict__ bi,
        const float* __restrict__ Wo, const float* __restrict__ bo,
        float* __restrict__ out) {
    extern __shared__ float sm[];
    float* sW   = sm;
    float* sWo  = sm + 20480;
    float* sBia = sm + 20736;
    float* sU   = sm + 20992;
    float* sP   = sm + 31232;
    float* sCi  = sm + 41632;
    int tid = threadIdx.x;

    for (int i = tid; i < 4096; i += 320) {
        sW[i]            = Wg[i];
        sW[4096 + i]     = Wa[i];
        sW[2 * 4096 + i] = Wl[i];
        sW[3 * 4096 + i] = Wr[i];
        sW[4 * 4096 + i] = Wi[i];
    }
    if (tid < 256) sWo[tid] = Wo[tid];
    if (tid < 64) {
        sBia[tid] = bg[tid]; sBia[64 + tid] = ba[tid];
        sBia[128 + tid] = bl[tid]; sBia[192 + tid] = bi[tid];
    }
    float bout = bo[0];
    __syncthreads();

    int wwid = tid >> 5, lane = tid & 31;
    int p = wwid >> 1, ng = wwid & 1;          // p in 0..4
    int tx = lane & 15, ty = lane >> 4;
    const float* Wp = sW + p * 4096;
    const float* Ub = sU + p * 2048 + ng * 16 + ty * 8;

    const float4* gsrc[4] = { (const float4*)g_aggG, (const float4*)g_aggA,
                              (const float4*)g_aggS, (const float4*)x };

    for (int tile = blockIdx.x; tile < N_TILES; tile += gridDim.x) {
        int base = tile * 32;
        if (tid < 32) {
            int n = base + tid;
            sCi[tid] = (n < N_NODES) ? 1.0f / fmaxf((float)g_cnt[n], 1.0f) : 0.f;
        }
        __syncthreads();
        // stage inputs transposed: 5 panels x 32 nodes x 16 float4-chunks
        for (int idx = tid; idx < 2560; idx += 320) {
            int a = idx >> 9, rem = idx & 511;
            int nl = rem & 31, kq = rem >> 5;
            int n = base + nl;
            float4 v = make_float4(0.f, 0.f, 0.f, 0.f);
            if (n < N_NODES) {
                if (a < 4) {
                    v = gsrc[a][n * 16 + kq];
                    if (a == 2) {
                        float ci = sCi[nl];
                        v.x *= ci; v.y *= ci; v.z *= ci; v.w *= ci;
                    }
                } else {
                    float4 t1 = gsrc[3][n * 16 + kq];
                    float4 t2 = gsrc[2][n * 16 + kq];
                    v = make_float4(t1.x + t2.x, t1.y + t2.y, t1.z + t2.z, t1.w + t2.w);
                }
            }
            float* dstp = sU + a * 2048 + (kq * 4) * 32 + nl;
            dstp[0]  = v.x; dstp[32] = v.y; dstp[64] = v.z; dstp[96] = v.w;
        }
        __syncthreads();

        float acc[8][4];
        #pragma unroll
        for (int r = 0; r < 8; r++)
            #pragma unroll
            for (int jj = 0; jj < 4; jj++) acc[r][jj] = 0.f;

        #pragma unroll 4
        for (int k = 0; k < 64; k++) {
            float4 u0 = *(const float4*)(Ub + k * 32);
            float4 u1 = *(const float4*)(Ub + k * 32 + 4);
            float4 wv = *(const float4*)(Wp + k * 64 + tx * 4);
            float ur[8] = {u0.x, u0.y, u0.z, u0.w, u1.x, u1.y, u1.z, u1.w};
            #pragma unroll
            for (int r = 0; r < 8; r++) {
                acc[r][0] = fmaf(ur[r], wv.x, acc[r][0]);
                acc[r][1] = fmaf(ur[r], wv.y, acc[r][1]);
                acc[r][2] = fmaf(ur[r], wv.z, acc[r][2]);
                acc[r][3] = fmaf(ur[r], wv.w, acc[r][3]);
            }
        }
        #pragma unroll
        for (int r = 0; r < 8; r++) {
            int nl = ng * 16 + ty * 8 + r;
            float* pp = sP + (p * 32 + nl) * 65 + tx * 4;
            pp[0] = acc[r][0]; pp[1] = acc[r][1]; pp[2] = acc[r][2]; pp[3] = acc[r][3];
        }
        __syncthreads();

        if (tid < 256) {
            int nl = tid >> 3, jb = tid & 7;
            float z = 0.f;
            #pragma unroll
            for (int jj = 0; jj < 8; jj++) {
                int j = jb * 8 + jj;
                float vg = sP[(0 * 32 + nl) * 65 + j] + sBia[j];
                float va2 = sP[(1 * 32 + nl) * 65 + j] + sBia[64 + j];
                float vs = sP[(2 * 32 + nl) * 65 + j] + sP[(3 * 32 + nl) * 65 + j] + sBia[128 + j];
                float vi = sP[(4 * 32 + nl) * 65 + j] + sBia[192 + j];
                z += fmaxf(vg, 0.f) * sWo[j] + fmaxf(va2, 0.f) * sWo[64 + j]
                   + fmaxf(vs, 0.f) * sWo[128 + j] + fmaxf(vi, 0.f) * sWo[192 + j];
            }
            z += __shfl_down_sync(0xffffffffu, z, 4);
            z += __shfl_down_sync(0xffffffffu, z, 2);
            z += __shfl_down_sync(0xffffffffu, z, 1);
            if ((tid & 7) == 0 && base + nl < N_NODES)
                out[base + nl] = 1.0f / (1.0f + expf(-(z + bout)));
        }
        __syncthreads();
    }
}

// ---------------- launch ----------------
extern "C" void kernel_launch(void* const* d_in, const int* in_sizes, int n_in,
                              void* d_out, int out_size) {
    const float* x    = (const float*)d_in[0];
    const void*  ei   = d_in[1];
    const float* Wg   = (const float*)d_in[2];
    const float* bg   = (const float*)d_in[3];
    const float* Wa   = (const float*)d_in[4];
    const float* asrc = (const float*)d_in[5];
    const float* adst = (const float*)d_in[6];
    const float* ba   = (const float*)d_in[7];
    const float* Wl   = (const float*)d_in[8];
    const float* bl   = (const float*)d_in[9];
    const float* Wr   = (const float*)d_in[10];
    const float* Wi   = (const float*)d_in[11];
    const float* bi   = (const float*)d_in[12];
    const float* Wo   = (const float*)d_in[13];
    const float* bo   = (const float*)d_in[14];
    float* out = (float*)d_out;

    cudaFuncSetAttribute(k_final, cudaFuncAttributeMaxDynamicSharedMemorySize, KF_SMEM_BYTES);

    void* cnt_ptr = nullptr;
    cudaGetSymbolAddress(&cnt_ptr, g_cnt);
    cudaMemsetAsync(cnt_ptr, 0, (N_NODES + 1) * sizeof(int), 0);

    k_convert<<<2048, 256>>>(ei, x, Wa, asrc, adst);                       // 0
    k_rowassign<<<(N_NODES + 255) / 256, 256>>>();                         // 1
    k_scatter<<<1024, 256>>>();                                            // 2
    k_agg<<<(N_NODES * 32 + 255) / 256, 256>>>(x);                         // 3 (profiled)
    k_final<<<148, 320, KF_SMEM_BYTES>>>(x, Wg, bg, Wa, ba, Wl, bl, Wr,    // 4
                                         Wi, bi, Wo, bo, out);
}

// round 8
// speedup vs baseline: 1.0233x; 1.0233x over previous
#include <cuda_runtime.h>

#define N_NODES 50000
#define N_EDGES 800000
#define FDIM 64
#define N_TILES ((N_NODES + 31) / 32)   // 1563

// ---------------- device scratch ----------------
__device__ int   g_src[N_EDGES];
__device__ int   g_dst[N_EDGES];
__device__ int   g_csrc[N_EDGES];          // CSR: src ids grouped by dst
__device__ int   g_row[N_NODES];           // CSR slice start per dst (arbitrary order)
__device__ int   g_cnt[N_NODES + 1];       // in-degree histogram; [N] = global offset counter
__device__ int   g_cur[N_NODES];           // scatter cursors
__device__ __align__(16) float g_aggG[N_NODES * FDIM];
__device__ __align__(16) float g_aggA[N_NODES * FDIM];
__device__ __align__(16) float g_aggS[N_NODES * FDIM];
__device__ float g_ssrc[N_NODES];
__device__ float g_sdst[N_NODES];
__device__ float g_dinv[N_NODES];

__device__ __forceinline__ float lrelu(float v) { return v > 0.f ? v : 0.2f * v; }

// ---------------- 0: dtype-detect + convert + histogram + per-node attn scalars ----------------
// int64 detection: ids < 50000 so high 32-bit words are 0; if int32, the odd
// words are 64 random ids (all-zero prob ~ (1/50000)^64 ~ 0).
__global__ void k_convert(const void* __restrict__ ei, const float* __restrict__ x,
                          const float* __restrict__ Wa, const float* __restrict__ as_,
                          const float* __restrict__ ad_) {
    __shared__ int s_is64;
    __shared__ float sva[FDIM], svb[FDIM];
    const unsigned int* w = (const unsigned int*)ei;
    int gid = blockIdx.x * blockDim.x + threadIdx.x;

    if (threadIdx.x == 0) {
        int z = 1;
        for (int i = 0; i < 64; i++) if (w[2 * i + 1] != 0u) { z = 0; break; }
        s_is64 = z;
    }
    if (blockIdx.x * blockDim.x < N_NODES) {
        if (threadIdx.x < FDIM) {
            int k = threadIdx.x;
            float va = 0.f, vb = 0.f;
            #pragma unroll 8
            for (int j = 0; j < FDIM; j++) {
                float wv = Wa[k * FDIM + j];
                va = fmaf(wv, as_[j], va);
                vb = fmaf(wv, ad_[j], vb);
            }
            sva[k] = va;
            svb[k] = vb;
        }
        __syncthreads();
        if (gid < N_NODES) {
            const float4* xr = (const float4*)(x + (size_t)gid * FDIM);
            float ss = 0.f, sd = 0.f;
            #pragma unroll
            for (int i = 0; i < FDIM / 4; i++) {
                float4 v = xr[i];
                ss = fmaf(v.x, sva[4*i], fmaf(v.y, sva[4*i+1], fmaf(v.z, sva[4*i+2], fmaf(v.w, sva[4*i+3], ss))));
                sd = fmaf(v.x, svb[4*i], fmaf(v.y, svb[4*i+1], fmaf(v.z, svb[4*i+2], fmaf(v.w, svb[4*i+3], sd))));
            }
            g_ssrc[gid] = ss;
            g_sdst[gid] = sd;
        }
    } else {
        __syncthreads();
    }
    int is64 = s_is64;
    int stride = gridDim.x * blockDim.x;
    for (int i = gid; i < 2 * N_EDGES; i += stride) {
        int v;
        if (is64) v = (int)((const long long*)ei)[i];
        else      v = ((const int*)ei)[i];
        if (i < N_EDGES) g_src[i] = v;
        else {
            g_dst[i - N_EDGES] = v;
            atomicAdd(&g_cnt[v], 1);
        }
    }
}

// ---------------- 1: row-slice assignment (block scan + 1 atomic per block) ----------------
__global__ void k_rowassign() {
    __shared__ int s_warp[8];
    __shared__ int s_base;
    int tid = threadIdx.x;
    int n = blockIdx.x * 256 + tid;
    int lane = tid & 31, wid = tid >> 5;
    int c = (n < N_NODES) ? g_cnt[n] : 0;
    int v = c;
    #pragma unroll
    for (int off = 1; off < 32; off <<= 1) {
        int u = __shfl_up_sync(0xffffffffu, v, off);
        if (lane >= off) v += u;
    }
    if (lane == 31) s_warp[wid] = v;
    __syncthreads();
    if (tid < 8) {
        int pv = s_warp[tid];
        #pragma unroll
        for (int off = 1; off < 8; off <<= 1) {
            int u = __shfl_up_sync(0xffu, pv, off);
            if (tid >= off) pv += u;
        }
        s_warp[tid] = pv;
        if (tid == 7) s_base = atomicAdd(&g_cnt[N_NODES], pv);
    }
    __syncthreads();
    int excl = v - c + (wid > 0 ? s_warp[wid - 1] : 0);
    if (n < N_NODES) {
        g_row[n] = s_base + excl;
        g_cur[n] = 0;
        g_dinv[n] = rsqrtf((float)c + 1.0f);
    }
}

// ---------------- 2: scatter src into CSR ----------------
__global__ void k_scatter() {
    int stride = gridDim.x * blockDim.x;
    for (int e = blockIdx.x * blockDim.x + threadIdx.x; e < N_EDGES; e += stride) {
        int d = g_dst[e];
        int pos = g_row[d] + atomicAdd(&g_cur[d], 1);
        g_csrc[pos] = g_src[e];
    }
}

// ---------------- 3: warp-per-node aggregation (R5 shuffle version — 40 regs, high occ) ----------------
__global__ void __launch_bounds__(256) k_agg(const float* __restrict__ x) {
    int wid = (blockIdx.x * blockDim.x + threadIdx.x) >> 5;
    int lane = threadIdx.x & 31;
    if (wid >= N_NODES) return;
    int d = wid;
    int row = g_row[d], end = row + g_cnt[d];
    float sd = g_sdst[d];
    float dvd = g_dinv[d];
    int q = lane & 15, half = lane >> 4;

    float4 aG = make_float4(0.f, 0.f, 0.f, 0.f);
    float4 aA = aG, aS = aG;
    float denom = 0.f;

    for (int base = row; base < end; base += 32) {
        int m = min(32, end - base);
        int   s_r = 0;
        float we_r = 0.f, wg_r = 0.f;
        if (lane < m) {
            s_r = g_csrc[base + lane];
            we_r = expf(lrelu(g_ssrc[s_r] + sd));
            wg_r = g_dinv[s_r] * dvd;
            denom += we_r;
        }
        for (int i2 = 0; i2 < m; i2 += 2) {
            int i = i2 + half;
            int ic = (i < m) ? i : 0;
            int   s  = __shfl_sync(0xffffffffu, s_r, ic);
            float we = __shfl_sync(0xffffffffu, we_r, ic);
            float wg = __shfl_sync(0xffffffffu, wg_r, ic);
            if (i < m) {
                float4 xv = ((const float4*)x)[s * 16 + q];
                aG.x = fmaf(wg, xv.x, aG.x); aG.y = fmaf(wg, xv.y, aG.y);
                aG.z = fmaf(wg, xv.z, aG.z); aG.w = fmaf(wg, xv.w, aG.w);
                aA.x = fmaf(we, xv.x, aA.x); aA.y = fmaf(we, xv.y, aA.y);
                aA.z = fmaf(we, xv.z, aA.z); aA.w = fmaf(we, xv.w, aA.w);
                aS.x += xv.x; aS.y += xv.y; aS.z += xv.z; aS.w += xv.w;
            }
        }
    }

    #pragma unroll
    for (int off = 16; off > 0; off >>= 1)
        denom += __shfl_xor_sync(0xffffffffu, denom, off);
    float selfexp = expf(lrelu(g_ssrc[d] + sd));
    float rdenom = 1.0f / (denom + selfexp);

    #pragma unroll
    for (int c = 0; c < 12; c++) {
        float* p = (c < 4) ? (&aG.x + c) : (c < 8) ? (&aA.x + (c - 4)) : (&aS.x + (c - 8));
        *p += __shfl_xor_sync(0xffffffffu, *p, 16);
    }
    if (half == 0) {
        float4 xd = ((const float4*)x)[d * 16 + q];
        float wd = dvd * dvd;
        float4 G = make_float4(fmaf(wd, xd.x, aG.x), fmaf(wd, xd.y, aG.y),
                               fmaf(wd, xd.z, aG.z), fmaf(wd, xd.w, aG.w));
        float4 A = make_float4((aA.x + selfexp * xd.x) * rdenom, (aA.y + selfexp * xd.y) * rdenom,
                               (aA.z + selfexp * xd.z) * rdenom, (aA.w + selfexp * xd.w) * rdenom);
        ((float4*)g_aggG)[d * 16 + q] = G;
        ((float4*)g_aggA)[d * 16 + q] = A;
        ((float4*)g_aggS)[d * 16 + q] = aS;
    }
}

// ---------------- 4: 5-panel GEMM, 640 threads (20 warps = 5 panels x 4 node groups) ----------------
// panels: 0: aggG@Wg  1: aggA@Wa  2: (aggS*ci)@Wl  3: x@Wr  4: (x+aggS)@Wi
// smem float layout:
//   sW   [5][64][64]      @ 0        (20480)
//   sWo  [4][64]          @ 20480    (256)
//   sBias[4][64]          @ 20736    (256)
//   sU   [5][64][32]      @ 20992    (10240)  inputs transposed [k][node]
//   sP   [5][32][65]      @ 31232    (10400)  panel outputs, padded rows
//   sCi  [32]             @ 41632    (32)
#define KF_SMEM_FLOATS 41664
#define KF_SMEM_BYTES (KF_SMEM_FLOATS * 4)

__global__ void __launch_bounds__(640, 1) k_final(
        const float* __restrict__ x,
        const float* __restrict__ Wg, const float* __restrict__ bg,
        const float* __restrict__ Wa, const float* __restrict__ ba,
        const float* __restrict__ Wl, const float* __restrict__ bl,
        const float* __restrict__ Wr,
        const float* __restrict__ Wi, const float* __restrict__ bi,
        const float* __restrict__ Wo, const float* __restrict__ bo,
        float* __restrict__ out) {
    extern __shared__ float sm[];
    float* sW   = sm;
    float* sWo  = sm + 20480;
    float* sBia = sm + 20736;
    float* sU   = sm + 20992;
    float* sP   = sm + 31232;
    float* sCi  = sm + 41632;
    int tid = threadIdx.x;

    for (int i = tid; i < 4096; i += 640) {
        sW[i]            = Wg[i];
        sW[4096 + i]     = Wa[i];
        sW[2 * 4096 + i] = Wl[i];
        sW[3 * 4096 + i] = Wr[i];
        sW[4 * 4096 + i] = Wi[i];
    }
    if (tid >= 4096 - 640 * 6 && false) {}
    if (tid < 256) sWo[tid] = Wo[tid];
    if (tid < 64) {
        sBia[tid] = bg[tid]; sBia[64 + tid] = ba[tid];
        sBia[128 + tid] = bl[tid]; sBia[192 + tid] = bi[tid];
    }
    float bout = bo[0];
    __syncthreads();

    int wwid = tid >> 5, lane = tid & 31;
    int p = wwid >> 2, ng = wwid & 3;          // p in 0..4, ng in 0..3 (node group of 8)
    int tx = lane & 15, ty = lane >> 4;        // tx: output group (4 outs), ty: node subgroup (4 nodes)
    const float* Wp = sW + p * 4096;
    const float* Ub = sU + p * 2048 + ng * 8 + ty * 4;

    const float4* gsrc[4] = { (const float4*)g_aggG, (const float4*)g_aggA,
                              (const float4*)g_aggS, (const float4*)x };

    for (int tile = blockIdx.x; tile < N_TILES; tile += gridDim.x) {
        int base = tile * 32;
        if (tid < 32) {
            int n = base + tid;
            sCi[tid] = (n < N_NODES) ? 1.0f / fmaxf((float)g_cnt[n], 1.0f) : 0.f;
        }
        __syncthreads();
        // stage inputs transposed: 5 panels x 32 nodes x 16 float4-chunks
        for (int idx = tid; idx < 2560; idx += 640) {
            int a = idx >> 9, rem = idx & 511;
            int nl = rem & 31, kq = rem >> 5;
            int n = base + nl;
            float4 v = make_float4(0.f, 0.f, 0.f, 0.f);
            if (n < N_NODES) {
                if (a < 4) {
                    v = gsrc[a][n * 16 + kq];
                    if (a == 2) {
                        float ci = sCi[nl];
                        v.x *= ci; v.y *= ci; v.z *= ci; v.w *= ci;
                    }
                } else {
                    float4 t1 = gsrc[3][n * 16 + kq];
                    float4 t2 = gsrc[2][n * 16 + kq];
                    v = make_float4(t1.x + t2.x, t1.y + t2.y, t1.z + t2.z, t1.w + t2.w);
                }
            }
            float* dstp = sU + a * 2048 + (kq * 4) * 32 + nl;
            dstp[0]  = v.x; dstp[32] = v.y; dstp[64] = v.z; dstp[96] = v.w;
        }
        __syncthreads();

        float acc[4][4];
        #pragma unroll
        for (int r = 0; r < 4; r++)
            #pragma unroll
            for (int jj = 0; jj < 4; jj++) acc[r][jj] = 0.f;

        #pragma unroll 8
        for (int k = 0; k < 64; k++) {
            float4 u = *(const float4*)(Ub + k * 32);
            float4 wv = *(const float4*)(Wp + k * 64 + tx * 4);
            float ur[4] = {u.x, u.y, u.z, u.w};
            #pragma unroll
            for (int r = 0; r < 4; r++) {
                acc[r][0] = fmaf(ur[r], wv.x, acc[r][0]);
                acc[r][1] = fmaf(ur[r], wv.y, acc[r][1]);
                acc[r][2] = fmaf(ur[r], wv.z, acc[r][2]);
                acc[r][3] = fmaf(ur[r], wv.w, acc[r][3]);
            }
        }
        #pragma unroll
        for (int r = 0; r < 4; r++) {
            int nl = ng * 8 + ty * 4 + r;
            float* pp = sP + (p * 32 + nl) * 65 + tx * 4;
            pp[0] = acc[r][0]; pp[1] = acc[r][1]; pp[2] = acc[r][2]; pp[3] = acc[r][3];
        }
        __syncthreads();

        if (tid < 256) {
            int nl = tid >> 3, jb = tid & 7;
            float z = 0.f;
            #pragma unroll
            for (int jj = 0; jj < 8; jj++) {
                int j = jb * 8 + jj;
                float vg = sP[(0 * 32 + nl) * 65 + j] + sBia[j];
                float va2 = sP[(1 * 32 + nl) * 65 + j] + sBia[64 + j];
                float vs = sP[(2 * 32 + nl) * 65 + j] + sP[(3 * 32 + nl) * 65 + j] + sBia[128 + j];
                float vi = sP[(4 * 32 + nl) * 65 + j] + sBia[192 + j];
                z += fmaxf(vg, 0.f) * sWo[j] + fmaxf(va2, 0.f) * sWo[64 + j]
                   + fmaxf(vs, 0.f) * sWo[128 + j] + fmaxf(vi, 0.f) * sWo[192 + j];
            }
            z += __shfl_down_sync(0xffffffffu, z, 4);
            z += __shfl_down_sync(0xffffffffu, z, 2);
            z += __shfl_down_sync(0xffffffffu, z, 1);
            if ((tid & 7) == 0 && base + nl < N_NODES)
                out[base + nl] = 1.0f / (1.0f + expf(-(z + bout)));
        }
        __syncthreads();
    }
}

// ---------------- launch ----------------
extern "C" void kernel_launch(void* const* d_in, const int* in_sizes, int n_in,
                              void* d_out, int out_size) {
    const float* x    = (const float*)d_in[0];
    const void*  ei   = d_in[1];
    const float* Wg   = (const float*)d_in[2];
    const float* bg   = (const float*)d_in[3];
    const float* Wa   = (const float*)d_in[4];
    const float* asrc = (const float*)d_in[5];
    const float* adst = (const float*)d_in[6];
    const float* ba   = (const float*)d_in[7];
    const float* Wl   = (const float*)d_in[8];
    const float* bl   = (const float*)d_in[9];
    const float* Wr   = (const float*)d_in[10];
    const float* Wi   = (const float*)d_in[11];
    const float* bi   = (const float*)d_in[12];
    const float* Wo   = (const float*)d_in[13];
    const float* bo   = (const float*)d_in[14];
    float* out = (float*)d_out;

    cudaFuncSetAttribute(k_final, cudaFuncAttributeMaxDynamicSharedMemorySize, KF_SMEM_BYTES);

    void* cnt_ptr = nullptr;
    cudaGetSymbolAddress(&cnt_ptr, g_cnt);
    cudaMemsetAsync(cnt_ptr, 0, (N_NODES + 1) * sizeof(int), 0);

    k_convert<<<2048, 256>>>(ei, x, Wa, asrc, adst);                       // 0
    k_rowassign<<<(N_NODES + 255) / 256, 256>>>();                         // 1
    k_scatter<<<1024, 256>>>();                                            // 2
    k_agg<<<(N_NODES * 32 + 255) / 256, 256>>>(x);                         // 3 (profiled)
    k_final<<<148, 640, KF_SMEM_BYTES>>>(x, Wg, bg, Wa, ba, Wl, bl, Wr,    // 4
                                         Wi, bi, Wo, bo, out);
}